// round 6
// baseline (speedup 1.0000x reference)
#include <cuda_runtime.h>
#include <cuda_bf16.h>
#include <cstdint>

// RBF layer: out[n] = sum_m w[m] * exp(-dist(n,m)),
//   dist = x^T C x - 2 x^T C mu + mu^T C mu,  C_m = G_m G_m^T (symmetric).
// N=32768, M=2048, D=32.
//
// Round 6: symmetric triangle (R5) + packed fma.rn.f32x2 (FFMA2).
// Triangle rows start at the even-aligned diagonal (e_start = d & ~1) so every
// row is f32x2-pair aligned against x's natural pairs; rows padded to x4
// floats (total still 576). Blob: [0:576) tri, [576:608) bm2=-2*C*mu,
// [608] c=mu^T C mu, pad to 640. Structure otherwise identical to the
// PASSING Round-5 kernel (register prefetch, no cp.async).

#define DD 32
#define NN 32768
#define MM 2048
#define MSPLIT 8
#define BLOCK 128
#define BLOB 640  // floats per m (160 float4)

__device__ float g_pack[MM * BLOB];
__device__ float g_partial[MSPLIT * NN];

__host__ __device__ constexpr int estart(int d) { return d & ~1; }
__host__ __device__ constexpr int padlen2(int d) {
    return ((DD - estart(d) + 3) / 4) * 4;
}
__host__ __device__ constexpr int rowstart2(int d) {
    int s = 0;
    for (int k = 0; k < d; k++) s += padlen2(k);
    return s;  // rowstart2(32) == 576
}

// ---- packed f32x2 helpers --------------------------------------------------
__device__ __forceinline__ void fma2(uint64_t& acc, uint64_t a, uint64_t b) {
    asm("fma.rn.f32x2 %0, %1, %2, %0;" : "+l"(acc) : "l"(a), "l"(b));
}
__device__ __forceinline__ uint64_t dup2(float v) {
    uint64_t r;
    uint32_t u = __float_as_uint(v);
    asm("mov.b64 %0, {%1, %1};" : "=l"(r) : "r"(u));
    return r;
}
__device__ __forceinline__ uint64_t pack2(float lo, float hi) {
    uint64_t r;
    asm("mov.b64 %0, {%1, %2};" : "=l"(r) : "r"(__float_as_uint(lo)), "r"(__float_as_uint(hi)));
    return r;
}
__device__ __forceinline__ void unpack2(float& lo, float& hi, uint64_t v) {
    uint32_t a, b;
    asm("mov.b64 {%0, %1}, %2;" : "=r"(a), "=r"(b) : "l"(v));
    lo = __uint_as_float(a);
    hi = __uint_as_float(b);
}

// ---- Kernel 1: build packed blob for each m -------------------------------
__global__ __launch_bounds__(128) void prep_kernel(
    const float* __restrict__ gamma,
    const float* __restrict__ means) {
    __shared__ float Gs[DD * DD];
    __shared__ float Cs[DD * DD];
    __shared__ float mus[DD];
    __shared__ float bs[DD];

    const int m = blockIdx.x;
    const int tid = threadIdx.x;
    float* blob = g_pack + (size_t)m * BLOB;

    const float* gsrc = gamma + (size_t)m * DD * DD;
#pragma unroll
    for (int i = tid; i < DD * DD; i += 128) Gs[i] = gsrc[i];
    if (tid < DD) mus[tid] = means[(size_t)m * DD + tid];
    for (int i = tid; i < BLOB; i += 128) blob[i] = 0.0f;
    __syncthreads();

    for (int idx = tid; idx < 528; idx += 128) {
        int d = 0, rem = idx;
        while (rem >= DD - d) { rem -= DD - d; d++; }
        int e = d + rem;
        float c = 0.0f;
#pragma unroll
        for (int k = 0; k < DD; k++) c += Gs[d * DD + k] * Gs[e * DD + k];
        Cs[d * DD + e] = c;
        Cs[e * DD + d] = c;
        // even-aligned row layout
        int rs = 0;
        for (int k = 0; k < d; k++) rs += padlen2(k);
        blob[rs + (e - estart(d))] = (e == d) ? c : 2.0f * c;
    }
    __syncthreads();

    if (tid < DD) {
        float b = 0.0f;
#pragma unroll
        for (int e = 0; e < DD; e++) b += Cs[tid * DD + e] * mus[e];
        bs[tid] = b;
        blob[576 + tid] = -2.0f * b;
    }
    __syncthreads();

    if (tid == 0) {
        float c = 0.0f;
#pragma unroll
        for (int d = 0; d < DD; d++) c += bs[d] * mus[d];
        blob[608] = c;
    }
}

// ---- Kernel 2: main fused kernel ------------------------------------------
__global__ __launch_bounds__(BLOCK) void rbf_main_kernel(
    const float* __restrict__ x,
    const float* __restrict__ weights) {
    __shared__ __align__(16) float4 gs[2][BLOB / 4];  // 2 x 2.5 KB

    const int tid = threadIdx.x;
    const int n = blockIdx.x * BLOCK + tid;
    const int m0 = blockIdx.y * (MM / MSPLIT);
    const int m1 = m0 + (MM / MSPLIT);

    // x row: natural pairs xpp[j] = (x[2j], x[2j+1]); duplicated xdup[d].
    uint64_t xpp[DD / 2];
    uint64_t xdup[DD];
    {
        const float4* xp = reinterpret_cast<const float4*>(x + (size_t)n * DD);
#pragma unroll
        for (int i = 0; i < DD / 4; i++) {
            float4 v = xp[i];
            xpp[2 * i + 0] = pack2(v.x, v.y);
            xpp[2 * i + 1] = pack2(v.z, v.w);
            xdup[4 * i + 0] = dup2(v.x);
            xdup[4 * i + 1] = dup2(v.y);
            xdup[4 * i + 2] = dup2(v.z);
            xdup[4 * i + 3] = dup2(v.w);
        }
    }

    // Prologue: load tile m0 into buffer 0.
    {
        const float4* src = reinterpret_cast<const float4*>(g_pack + (size_t)m0 * BLOB);
        gs[0][tid] = src[tid];
        if (tid < 32) gs[0][128 + tid] = src[128 + tid];
    }
    __syncthreads();

    float acc = 0.0f;

    for (int m = m0; m < m1; ++m) {
        const int buf = (m - m0) & 1;

        // Prefetch next tile into registers (overlaps with compute).
        float4 p0, p1;
        const bool have_next = (m + 1 < m1);
        if (have_next) {
            const float4* src =
                reinterpret_cast<const float4*>(g_pack + (size_t)(m + 1) * BLOB);
            p0 = src[tid];
            if (tid < 32) p1 = src[128 + tid];
        }

        const float* tile = reinterpret_cast<const float*>(&gs[buf][0]);
        const ulonglong2* t2 = reinterpret_cast<const ulonglong2*>(tile);
        const float wm = __ldg(&weights[m]);

        // distp starts with the c term in the low lane.
        uint64_t distp = pack2(tile[608], 0.0f);

        // cross: x . bm2 (floats 576..607 = ulonglong2 indices 144..151)
#pragma unroll
        for (int j = 0; j < 8; j++) {
            ulonglong2 v = t2[144 + j];  // LDS.128 broadcast
            fma2(distp, v.x, xpp[2 * j]);
            fma2(distp, v.y, xpp[2 * j + 1]);
        }

        // quad: even-aligned padded triangle rows
#pragma unroll
        for (int d = 0; d < DD; d++) {
            const int s4 = rowstart2(d) / 4;      // compile-time (loop unrolled)
            const int np4 = padlen2(d) / 4;
            const int pb = estart(d) / 2;
            uint64_t rp = 0;
#pragma unroll
            for (int g = 0; g < np4; g++) {
                ulonglong2 v = t2[s4 + g];  // LDS.128 broadcast
                fma2(rp, v.x, xpp[pb + 2 * g]);
                fma2(rp, v.y, xpp[pb + 2 * g + 1]);
            }
            fma2(distp, xdup[d], rp);
        }

        float dl, dh;
        unpack2(dl, dh, distp);
        acc += wm * __expf(-(dl + dh));

        // Commit prefetched tile into the other buffer.
        if (have_next) {
            __syncthreads();  // everyone done reading buf^1 (tile m-1)
            gs[buf ^ 1][tid] = p0;
            if (tid < 32) gs[buf ^ 1][128 + tid] = p1;
            __syncthreads();
        }
    }

    g_partial[blockIdx.y * NN + n] = acc;
}

// ---- Kernel 3: reduce partials --------------------------------------------
__global__ void reduce_kernel(float* __restrict__ out) {
    int n = blockIdx.x * blockDim.x + threadIdx.x;
    float s = 0.0f;
#pragma unroll
    for (int i = 0; i < MSPLIT; i++) s += g_partial[i * NN + n];
    out[n] = s;
}

extern "C" void kernel_launch(void* const* d_in, const int* in_sizes, int n_in,
                              void* d_out, int out_size) {
    const float* inputs = (const float*)d_in[0];   // [N, D]
    const float* gamma = (const float*)d_in[1];    // [M, D, D]
    const float* means = (const float*)d_in[2];    // [M, D]
    const float* weights = (const float*)d_in[3];  // [M]
    float* out = (float*)d_out;                    // [N, 1]

    prep_kernel<<<MM, 128>>>(gamma, means);
    dim3 grid(NN / BLOCK, MSPLIT);
    rbf_main_kernel<<<grid, BLOCK>>>(inputs, weights);
    reduce_kernel<<<NN / 256, 256>>>(out);
}

// round 8
// speedup vs baseline: 1.7191x; 1.7191x over previous
#include <cuda_runtime.h>
#include <cuda_fp16.h>
#include <cstdint>

// RBF layer: out[n] = sum_m w[m] * exp(-dist(n,m)),
//   dist = x^T C x - 2 x^T C mu + mu^T C mu,  C = G G^T (symmetric).
// Expanded GEMM: dist = sum_k A[n,k]*B[m,k], K=561 padded to 576:
//   k<528: A=x_d*x_e (tri d<=e), B=(d==e?C_de:2C_de); 528+d: A=x_d, B=-2(Cmu)_d;
//   560: A=1, B=mu^T C mu.
// Tensor path: mma.sync.m16n8k16.f32.f16.f16.f32 (plain sm_103 target — tcgen05
// is unavailable: harness compiles at compute_103, no 'a' features).
// Precision: 2-limb fp16 split per operand, 3 limb-pair passes (00,01,10).
// exp predicated on dist<100 (reference fp32 exp flushes to 0 beyond ~104),
// dodging the 0.47ms MUFU floor.

#define DD 32
#define NN 32768
#define MM 2048
#define KS 576      // K padded (and gmem row stride)
#define KCH 32      // k per smem chunk
#define NCH 18      // 576/32
#define CSTR 40     // smem chunk row stride in fp16 (bank-conflict-free)
#define PLANE (128 * CSTR + 8)

__device__ __half g_A[(size_t)NN * 2 * KS];  // [n][limb][k]  75.5 MB
__device__ __half g_B[(size_t)MM * 2 * KS];  // [m][limb][k]  4.7 MB

// ---- helpers ---------------------------------------------------------------
__device__ __forceinline__ void tri_pair(int k, int& d, int& e) {
    int dd = 0, rem = k;
    while (rem >= DD - dd) { rem -= DD - dd; dd++; }
    d = dd;
    e = dd + rem;
}

__device__ __forceinline__ void split2(float f, __half& h0, __half& h1) {
    h0 = __float2half_rn(f);
    h1 = __float2half_rn(f - __half2float(h0));
}

__device__ __forceinline__ void mma16816(float* c, const uint32_t* a,
                                         const uint32_t* b) {
    asm("mma.sync.aligned.m16n8k16.row.col.f32.f16.f16.f32 "
        "{%0,%1,%2,%3}, {%4,%5,%6,%7}, {%8,%9}, {%0,%1,%2,%3};"
        : "+f"(c[0]), "+f"(c[1]), "+f"(c[2]), "+f"(c[3])
        : "r"(a[0]), "r"(a[1]), "r"(a[2]), "r"(a[3]), "r"(b[0]), "r"(b[1]));
}

// ---- Prep A: per-n features, 2 fp16 limbs. One warp per n. ----------------
__global__ __launch_bounds__(128) void prep_a_kernel(const float* __restrict__ x) {
    const int warp = threadIdx.x / 32, lane = threadIdx.x % 32;
    const int n = blockIdx.x * 4 + warp;
    const float xv = x[(size_t)n * DD + lane];
    __half* o0 = g_A + ((size_t)n * 2 + 0) * KS;
    __half* o1 = g_A + ((size_t)n * 2 + 1) * KS;

#pragma unroll 1
    for (int j = 0; j < KS / 32; j++) {  // 18 uniform iterations, no divergence
        const int k = j * 32 + lane;
        int d = 0, e = 0;
        if (k < 528) tri_pair(k, d, e);
        float fd = __shfl_sync(0xFFFFFFFFu, xv, d);
        float fe = __shfl_sync(0xFFFFFFFFu, xv, e);
        float f;
        if (k < 528) f = fd * fe;
        else if (k < 560) f = __shfl_sync(0xFFFFFFFFu, xv, k - 528);
        else if (k == 560) f = 1.0f;
        else f = 0.0f;
        __half h0, h1;
        split2(f, h0, h1);
        o0[k] = h0;
        o1[k] = h1;
    }
}

// ---- Prep B: per-m features, 2 fp16 limbs. One CTA per m. -----------------
__global__ __launch_bounds__(128) void prep_b_kernel(const float* __restrict__ gamma,
                                                     const float* __restrict__ means) {
    __shared__ float Gs[DD * DD];
    __shared__ float mus[DD];
    __shared__ float sv[DD];  // s = G^T mu
    __shared__ float bv[DD];  // b = C mu = G s
    __shared__ float cval;

    const int m = blockIdx.x;
    const int tid = threadIdx.x;
    const float* gsrc = gamma + (size_t)m * DD * DD;
#pragma unroll
    for (int i = tid; i < DD * DD; i += 128) Gs[i] = gsrc[i];
    if (tid < DD) mus[tid] = means[(size_t)m * DD + tid];
    __syncthreads();

    if (tid < DD) {  // s_k = sum_e mu_e G[e][k]
        float s = 0.0f;
#pragma unroll
        for (int e = 0; e < DD; e++) s += mus[e] * Gs[e * DD + tid];
        sv[tid] = s;
    }
    __syncthreads();
    if (tid < DD) {  // b_d = G_d . s
        float b = 0.0f;
#pragma unroll
        for (int k = 0; k < DD; k++) b += Gs[tid * DD + k] * sv[k];
        bv[tid] = b;
    }
    __syncthreads();
    if (tid == 0) {
        float c = 0.0f;
#pragma unroll
        for (int d = 0; d < DD; d++) c += bv[d] * mus[d];
        cval = c;
    }
    __syncthreads();

    __half* o0 = g_B + ((size_t)m * 2 + 0) * KS;
    __half* o1 = g_B + ((size_t)m * 2 + 1) * KS;
    for (int k = tid; k < KS; k += 128) {
        float f;
        if (k < 528) {
            int d, e;
            tri_pair(k, d, e);
            float cde = 0.0f;
#pragma unroll
            for (int q = 0; q < DD; q++) cde += Gs[d * DD + q] * Gs[e * DD + q];
            f = (d == e) ? cde : 2.0f * cde;
        } else if (k < 560) {
            f = -2.0f * bv[k - 528];
        } else if (k == 560) {
            f = cval;
        } else {
            f = 0.0f;
        }
        __half h0, h1;
        split2(f, h0, h1);
        o0[k] = h0;
        o1[k] = h1;
    }
}

// ---- Main: 128n x 128m tiles on mma.sync, fused exp epilogue --------------
__global__ __launch_bounds__(256) void rbf_mma_kernel(const float* __restrict__ w,
                                                      float* __restrict__ out) {
    __shared__ __half As[2 * PLANE];  // [limb][row 0..127][CSTR]
    __shared__ __half Bs[2 * PLANE];
    __shared__ float ws[128];

    const int tid = threadIdx.x;
    const int warp = tid >> 5, lane = tid & 31;
    const int n0 = blockIdx.x * 128;
    const int lrow = tid >> 1;   // load row 0..127
    const int llimb = tid & 1;   // load limb

    float accR0 = 0.0f, accR1 = 0.0f;

    for (int mb = 0; mb < MM / 128; mb++) {
        __syncthreads();  // previous epilogue finished reading ws
        if (tid < 128) ws[tid] = __ldg(w + mb * 128 + tid);

        float c[16][4];
#pragma unroll
        for (int j = 0; j < 16; j++) {
            c[j][0] = 0.0f; c[j][1] = 0.0f; c[j][2] = 0.0f; c[j][3] = 0.0f;
        }

        for (int ch = 0; ch < NCH; ch++) {
            __syncthreads();  // previous chunk's reads done
            {
                const __half* asrc =
                    g_A + ((size_t)(n0 + lrow) * 2 + llimb) * KS + ch * KCH;
                const __half* bsrc =
                    g_B + ((size_t)(mb * 128 + lrow) * 2 + llimb) * KS + ch * KCH;
                __half* adst = As + llimb * PLANE + lrow * CSTR;
                __half* bdst = Bs + llimb * PLANE + lrow * CSTR;
#pragma unroll
                for (int q = 0; q < 4; q++) {
                    *reinterpret_cast<float4*>(adst + q * 8) =
                        *reinterpret_cast<const float4*>(asrc + q * 8);
                    *reinterpret_cast<float4*>(bdst + q * 8) =
                        *reinterpret_cast<const float4*>(bsrc + q * 8);
                }
            }
            __syncthreads();

#pragma unroll
            for (int ks = 0; ks < 2; ks++) {
                const int k0 = ks * 16;
                uint32_t afr[2][4];
#pragma unroll
                for (int l = 0; l < 2; l++) {
                    const __half* ap = As + l * PLANE +
                                       (warp * 16 + (lane >> 2)) * CSTR + k0 +
                                       (lane & 3) * 2;
                    afr[l][0] = *reinterpret_cast<const uint32_t*>(ap);
                    afr[l][1] = *reinterpret_cast<const uint32_t*>(ap + 8 * CSTR);
                    afr[l][2] = *reinterpret_cast<const uint32_t*>(ap + 8);
                    afr[l][3] = *reinterpret_cast<const uint32_t*>(ap + 8 * CSTR + 8);
                }
#pragma unroll
                for (int j = 0; j < 16; j++) {
                    uint32_t bfr[2][2];
#pragma unroll
                    for (int l = 0; l < 2; l++) {
                        const __half* bp = Bs + l * PLANE +
                                           (j * 8 + (lane >> 2)) * CSTR + k0 +
                                           (lane & 3) * 2;
                        bfr[l][0] = *reinterpret_cast<const uint32_t*>(bp);
                        bfr[l][1] = *reinterpret_cast<const uint32_t*>(bp + 8);
                    }
                    mma16816(c[j], afr[0], bfr[0]);  // limb pair (0,0)
                    mma16816(c[j], afr[0], bfr[1]);  // (0,1)
                    mma16816(c[j], afr[1], bfr[0]);  // (1,0)
                }
            }
        }

        // Epilogue: acc += w * exp(-dist), predicated (ref fp32 exp is 0 there).
#pragma unroll
        for (int j = 0; j < 16; j++) {
            const int col = j * 8 + (lane & 3) * 2;
            const float w0 = ws[col], w1 = ws[col + 1];
            if (c[j][0] < 100.0f) accR0 += w0 * __expf(-c[j][0]);
            if (c[j][1] < 100.0f) accR0 += w1 * __expf(-c[j][1]);
            if (c[j][2] < 100.0f) accR1 += w0 * __expf(-c[j][2]);
            if (c[j][3] < 100.0f) accR1 += w1 * __expf(-c[j][3]);
        }
    }

    // Reduce over the 4 lanes sharing each output row.
    accR0 += __shfl_xor_sync(0xFFFFFFFFu, accR0, 1);
    accR0 += __shfl_xor_sync(0xFFFFFFFFu, accR0, 2);
    accR1 += __shfl_xor_sync(0xFFFFFFFFu, accR1, 1);
    accR1 += __shfl_xor_sync(0xFFFFFFFFu, accR1, 2);
    if ((lane & 3) == 0) {
        const int r = warp * 16 + (lane >> 2);
        out[n0 + r] = accR0;
        out[n0 + r + 8] = accR1;
    }
}

extern "C" void kernel_launch(void* const* d_in, const int* in_sizes, int n_in,
                              void* d_out, int out_size) {
    const float* inputs = (const float*)d_in[0];   // [N, D]
    const float* gamma = (const float*)d_in[1];    // [M, D, D]
    const float* means = (const float*)d_in[2];    // [M, D]
    const float* weights = (const float*)d_in[3];  // [M]
    float* out = (float*)d_out;                    // [N, 1]

    prep_a_kernel<<<NN / 4, 128>>>(inputs);
    prep_b_kernel<<<MM, 128>>>(gamma, means);
    rbf_mma_kernel<<<NN / 128, 256>>>(weights, out);
}

// round 9
// speedup vs baseline: 1.8040x; 1.0494x over previous
#include <cuda_runtime.h>
#include <cuda_fp16.h>
#include <cstdint>

// RBF layer: out[n] = sum_m w[m]*exp(-dist), dist = sum_k A[n,k]B[m,k], K=561->576
// (triangle xx / x / 1 features vs C-triangle / -2Cmu / muCmu).
// mma.sync.m16n8k16 fp16, 2-limb split, 3 limb passes (00,01,10).
// Round 9: cp.async double-buffered K-chunks (KCH=16, 48KB static smem),
// MMA reordered for chain distance 8, tri-index tables for prep kernels.

#define DD 32
#define NN 32768
#define MM 2048
#define KS 576
#define KCH 16
#define NCHK 36        // 576/16
#define CSTR 24        // smem row stride in halfs (48B) -> conflict-free frags
#define PL (128 * CSTR)

__device__ __half g_A[(size_t)NN * 2 * KS];  // [n][limb][k]
__device__ __half g_B[(size_t)MM * 2 * KS];  // [m][limb][k]
__device__ int g_tabD[KS];
__device__ int g_tabE[KS];

// ---- helpers ---------------------------------------------------------------
__device__ __forceinline__ void split2(float f, __half& h0, __half& h1) {
    h0 = __float2half_rn(f);
    h1 = __float2half_rn(f - __half2float(h0));
}
__device__ __forceinline__ void mma16816(float* c, const uint32_t* a,
                                         const uint32_t* b) {
    asm("mma.sync.aligned.m16n8k16.row.col.f32.f16.f16.f32 "
        "{%0,%1,%2,%3}, {%4,%5,%6,%7}, {%8,%9}, {%0,%1,%2,%3};"
        : "+f"(c[0]), "+f"(c[1]), "+f"(c[2]), "+f"(c[3])
        : "r"(a[0]), "r"(a[1]), "r"(a[2]), "r"(a[3]), "r"(b[0]), "r"(b[1]));
}
__device__ __forceinline__ void cp16(uint32_t dst, const void* src) {
    asm volatile("cp.async.cg.shared.global [%0], [%1], 16;" ::"r"(dst), "l"(src));
}

// ---- Kernel 0: triangle index tables --------------------------------------
__global__ void prep_tri_kernel() {
    int k = threadIdx.x;
    if (k < 528) {
        int d = 0, rem = k;
        while (rem >= DD - d) { rem -= DD - d; d++; }
        g_tabD[k] = d;
        g_tabE[k] = d + rem;
    } else {
        g_tabD[k] = 0;
        g_tabE[k] = 0;
    }
}

// ---- Prep A: per-n features, 2 fp16 limbs. One warp per n. ----------------
__global__ __launch_bounds__(128) void prep_a_kernel(const float* __restrict__ x) {
    const int warp = threadIdx.x / 32, lane = threadIdx.x % 32;
    const int n = blockIdx.x * 4 + warp;
    const float xv = x[(size_t)n * DD + lane];
    __half* o0 = g_A + ((size_t)n * 2 + 0) * KS;
    __half* o1 = g_A + ((size_t)n * 2 + 1) * KS;

#pragma unroll 1
    for (int j = 0; j < KS / 32; j++) {
        const int k = j * 32 + lane;
        const int d = __ldg(&g_tabD[k]);
        const int e = __ldg(&g_tabE[k]);
        float fd = __shfl_sync(0xFFFFFFFFu, xv, d);
        float fe = __shfl_sync(0xFFFFFFFFu, xv, e);
        float f;
        if (k < 528) f = fd * fe;
        else if (k < 560) f = __shfl_sync(0xFFFFFFFFu, xv, k - 528);
        else if (k == 560) f = 1.0f;
        else f = 0.0f;
        __half h0, h1;
        split2(f, h0, h1);
        o0[k] = h0;
        o1[k] = h1;
    }
}

// ---- Prep B: per-m features, 2 fp16 limbs. One CTA per m. -----------------
__global__ __launch_bounds__(128) void prep_b_kernel(const float* __restrict__ gamma,
                                                     const float* __restrict__ means) {
    __shared__ float Gs[DD * DD];
    __shared__ float mus[DD];
    __shared__ float sv[DD];
    __shared__ float bv[DD];
    __shared__ float cval;

    const int m = blockIdx.x;
    const int tid = threadIdx.x;
    const float* gsrc = gamma + (size_t)m * DD * DD;
#pragma unroll
    for (int i = tid; i < DD * DD; i += 128) Gs[i] = gsrc[i];
    if (tid < DD) mus[tid] = means[(size_t)m * DD + tid];
    __syncthreads();

    if (tid < DD) {
        float s = 0.0f;
#pragma unroll
        for (int e = 0; e < DD; e++) s += mus[e] * Gs[e * DD + tid];
        sv[tid] = s;
    }
    __syncthreads();
    if (tid < DD) {
        float b = 0.0f;
#pragma unroll
        for (int k = 0; k < DD; k++) b += Gs[tid * DD + k] * sv[k];
        bv[tid] = b;
    }
    __syncthreads();
    if (tid == 0) {
        float c = 0.0f;
#pragma unroll
        for (int d = 0; d < DD; d++) c += bv[d] * mus[d];
        cval = c;
    }
    __syncthreads();

    __half* o0 = g_B + ((size_t)m * 2 + 0) * KS;
    __half* o1 = g_B + ((size_t)m * 2 + 1) * KS;
    for (int k = tid; k < KS; k += 128) {
        float f;
        if (k < 528) {
            const int d = g_tabD[k], e = g_tabE[k];
            float cde = 0.0f;
#pragma unroll
            for (int q = 0; q < DD; q++) cde += Gs[d * DD + q] * Gs[e * DD + q];
            f = (d == e) ? cde : 2.0f * cde;
        } else if (k < 560) {
            f = -2.0f * bv[k - 528];
        } else if (k == 560) {
            f = cval;
        } else {
            f = 0.0f;
        }
        __half h0, h1;
        split2(f, h0, h1);
        o0[k] = h0;
        o1[k] = h1;
    }
}

// ---- Main: 128n x 128m tiles, cp.async double-buffered --------------------
__global__ __launch_bounds__(256, 1) void rbf_mma_kernel(const float* __restrict__ w,
                                                         float* __restrict__ out) {
    // [buf][plane: A0,A1,B0,B1][128 rows * CSTR]  = 49152 bytes exactly
    __shared__ __half sb[2][4][PL];

    const int tid = threadIdx.x;
    const int warp = tid >> 5, lane = tid & 31;
    const int n0 = blockIdx.x * 128;

    // cp.async mapping: 256 thr x 4 x 16B = 16KB per chunk stage
    const int lp = tid >> 6;       // plane 0..3
    const int lu = tid & 63;       // 64 units per plane

    float accR0 = 0.0f, accR1 = 0.0f;

    for (int mb = 0; mb < MM / 128; mb++) {
        float c[16][4];
#pragma unroll
        for (int j = 0; j < 16; j++) {
            c[j][0] = 0.0f; c[j][1] = 0.0f; c[j][2] = 0.0f; c[j][3] = 0.0f;
        }

        // prologue: stage chunk 0 into buf 0
        {
#pragma unroll
            for (int q = 0; q < 4; q++) {
                const int unit = lu * 4 + q;
                const int row = unit >> 1, h = unit & 1;
                uint32_t dst = (uint32_t)__cvta_generic_to_shared(
                    &sb[0][lp][row * CSTR + h * 8]);
                const __half* src =
                    (lp < 2) ? g_A + ((size_t)(n0 + row) * 2 + lp) * KS + h * 8
                             : g_B + ((size_t)(mb * 128 + row) * 2 + (lp - 2)) * KS + h * 8;
                cp16(dst, src);
            }
            asm volatile("cp.async.commit_group;");
        }

        for (int ch = 0; ch < NCHK; ch++) {
            const int buf = ch & 1;
            if (ch + 1 < NCHK) {
                const int nb = buf ^ 1;
                const int ko = (ch + 1) * KCH;
#pragma unroll
                for (int q = 0; q < 4; q++) {
                    const int unit = lu * 4 + q;
                    const int row = unit >> 1, h = unit & 1;
                    uint32_t dst = (uint32_t)__cvta_generic_to_shared(
                        &sb[nb][lp][row * CSTR + h * 8]);
                    const __half* src =
                        (lp < 2)
                            ? g_A + ((size_t)(n0 + row) * 2 + lp) * KS + ko + h * 8
                            : g_B + ((size_t)(mb * 128 + row) * 2 + (lp - 2)) * KS + ko + h * 8;
                    cp16(dst, src);
                }
                asm volatile("cp.async.commit_group;");
                asm volatile("cp.async.wait_group 1;");
            } else {
                asm volatile("cp.async.wait_group 0;");
            }
            __syncthreads();

            // A fragments (both limbs)
            uint32_t afr[2][4];
#pragma unroll
            for (int l = 0; l < 2; l++) {
                const __half* ap =
                    &sb[buf][l][(warp * 16 + (lane >> 2)) * CSTR + (lane & 3) * 2];
                afr[l][0] = *reinterpret_cast<const uint32_t*>(ap);
                afr[l][1] = *reinterpret_cast<const uint32_t*>(ap + 8 * CSTR);
                afr[l][2] = *reinterpret_cast<const uint32_t*>(ap + 8);
                afr[l][3] = *reinterpret_cast<const uint32_t*>(ap + 8 * CSTR + 8);
            }

#pragma unroll
            for (int jb = 0; jb < 2; jb++) {
                uint32_t bfr[2][8][2];
#pragma unroll
                for (int l = 0; l < 2; l++) {
#pragma unroll
                    for (int jj = 0; jj < 8; jj++) {
                        const __half* bp =
                            &sb[buf][2 + l][((jb * 8 + jj) * 8 + (lane >> 2)) * CSTR +
                                            (lane & 3) * 2];
                        bfr[l][jj][0] = *reinterpret_cast<const uint32_t*>(bp);
                        bfr[l][jj][1] = *reinterpret_cast<const uint32_t*>(bp + 8);
                    }
                }
                // 3 limb passes, j-inner: dependency chain distance 8
#pragma unroll
                for (int jj = 0; jj < 8; jj++) mma16816(c[jb * 8 + jj], afr[0], bfr[0][jj]);
#pragma unroll
                for (int jj = 0; jj < 8; jj++) mma16816(c[jb * 8 + jj], afr[0], bfr[1][jj]);
#pragma unroll
                for (int jj = 0; jj < 8; jj++) mma16816(c[jb * 8 + jj], afr[1], bfr[0][jj]);
            }
            __syncthreads();
        }

        // Epilogue: acc += w * exp(-dist), predicated (fp32 exp is 0 beyond ~104)
#pragma unroll
        for (int j = 0; j < 16; j++) {
            const int col = mb * 128 + j * 8 + (lane & 3) * 2;
            const float w0 = __ldg(w + col), w1 = __ldg(w + col + 1);
            if (c[j][0] < 100.0f) accR0 += w0 * __expf(-c[j][0]);
            if (c[j][1] < 100.0f) accR0 += w1 * __expf(-c[j][1]);
            if (c[j][2] < 100.0f) accR1 += w0 * __expf(-c[j][2]);
            if (c[j][3] < 100.0f) accR1 += w1 * __expf(-c[j][3]);
        }
    }

    accR0 += __shfl_xor_sync(0xFFFFFFFFu, accR0, 1);
    accR0 += __shfl_xor_sync(0xFFFFFFFFu, accR0, 2);
    accR1 += __shfl_xor_sync(0xFFFFFFFFu, accR1, 1);
    accR1 += __shfl_xor_sync(0xFFFFFFFFu, accR1, 2);
    if ((lane & 3) == 0) {
        const int r = warp * 16 + (lane >> 2);
        out[n0 + r] = accR0;
        out[n0 + r + 8] = accR1;
    }
}

extern "C" void kernel_launch(void* const* d_in, const int* in_sizes, int n_in,
                              void* d_out, int out_size) {
    const float* inputs = (const float*)d_in[0];   // [N, D]
    const float* gamma = (const float*)d_in[1];    // [M, D, D]
    const float* means = (const float*)d_in[2];    // [M, D]
    const float* weights = (const float*)d_in[3];  // [M]
    float* out = (float*)d_out;                    // [N, 1]

    prep_tri_kernel<<<1, KS>>>();
    prep_a_kernel<<<NN / 4, 128>>>(inputs);
    prep_b_kernel<<<MM, 128>>>(gamma, means);
    rbf_mma_kernel<<<NN / 128, 256>>>(weights, out);
}